// round 7
// baseline (speedup 1.0000x reference)
#include <cuda_runtime.h>
#include <math.h>

// Problem constants (SPINN1: B=128, T=40, D_HID=512, D_TRK=256)
#define BB   128
#define TT   40
#define DD   512
#define TRK  256
#define CAP  (TT + 2)            // 42
#define TWOD (2 * DD)            // 1024
#define KTRK (3 * DD + TRK)      // 1792  (xT = [buf_h | s1_h | s2_h | th])
#define NTRK (4 * TRK)           // 1024
#define KRED (2 * DD + TRK)      // 1280  (W_red rows: [W_left | W_right | W_track])
#define KXR  (2 * DD)            // 1024  (xR = [s2_h | s1_h])
#define NRED (5 * DD)            // 2560
#define NBLK 148                 // persistent blocks (<= SM count)
// Phase A tiles: reduce-big 20 n-tiles x 8 splits (8 slabs) = 160,
//                tracker    8 n-tiles x 16 splits (7 slabs) = 128  -> 288
#define NT_A 288
#define NT_A_LAST 128            // last step: tracker only
// Phase C tiles: strk 20 n-tiles x 7 splits (2-3 slabs) = 140
#define NT_C 140

// ---------------- device state (no runtime allocation allowed) --------------
__device__ __align__(16) float g_stack[BB * CAP * TWOD];
__device__ __align__(16) float g_th[BB * TRK];
__device__ __align__(16) float g_tc[BB * TRK];
__device__ int   g_sptr[BB];
__device__ int   g_blen[BB];
__device__ __align__(16) float g_xT[BB * KTRK];
__device__ __align__(16) float g_xR[BB * KXR];
__device__ __align__(16) float g_gates[BB * NTRK];   // pre-biased, GEMM red-accum
__device__ __align__(16) float g_rin[BB * NRED];     // pre-biased, GEMM red-accum
__device__ int   g_trans[BB];
__device__ __align__(16) float g_Wtrk[NTRK * KTRK];  // [W_ih | W_hh] concat along K
__device__ __align__(16) float g_Wred[NRED * KRED];  // [W_left | W_right | W_track]
__device__ __align__(16) float g_btrk[NTRK];         // b_ih + b_hh
__device__ unsigned g_barCount;
__device__ volatile unsigned g_barEpoch;

__device__ __forceinline__ float sigf(float x) { return 1.0f / (1.0f + expf(-x)); }

typedef unsigned long long ull;
__device__ __forceinline__ ull packf2(float x, float y) {
    ull v; asm("mov.b64 %0, {%1,%2};" : "=l"(v) : "f"(x), "f"(y)); return v;
}
__device__ __forceinline__ float2 unpackf2(ull v) {
    float2 r; asm("mov.b64 {%0,%1}, %2;" : "=f"(r.x), "=f"(r.y) : "l"(v)); return r;
}
__device__ __forceinline__ void ffma2(ull& d, ull a, ull b) {
    asm("fma.rn.f32x2 %0, %1, %2, %0;" : "+l"(d) : "l"(a), "l"(b));
}
__device__ __forceinline__ void redadd(float* p, float v) {
    asm volatile("red.global.add.f32 [%0], %1;" :: "l"(p), "f"(v) : "memory");
}

// ---------------- grid-wide sense-reversing barrier --------------------------
__device__ __forceinline__ void grid_bar() {
    __syncthreads();
    if (threadIdx.x == 0) {
        __threadfence();
        unsigned e = g_barEpoch;
        unsigned v = atomicAdd(&g_barCount, 1u);
        if (v == (unsigned)(gridDim.x - 1)) {
            g_barCount = 0;
            __threadfence();
            g_barEpoch = e + 1;
        } else {
            while (g_barEpoch == e) { __nanosleep(32); }
            __threadfence();
        }
    }
    __syncthreads();
}

// ---------------- init: concat weights, init stack/state --------------------
__global__ void k_init(const float* __restrict__ buffers,
                       const float* __restrict__ W_ih, const float* __restrict__ W_hh,
                       const float* __restrict__ b_ih, const float* __restrict__ b_hh,
                       const float* __restrict__ W_left, const float* __restrict__ W_right,
                       const float* __restrict__ W_track) {
    int stride = gridDim.x * blockDim.x;
    int tid0 = blockIdx.x * blockDim.x + threadIdx.x;

    for (int idx = tid0; idx < NTRK * KTRK; idx += stride) {
        int n = idx / KTRK, k = idx - n * KTRK;
        g_Wtrk[idx] = (k < 3 * DD) ? W_ih[n * (3 * DD) + k] : W_hh[n * TRK + (k - 3 * DD)];
    }
    for (int idx = tid0; idx < NRED * KRED; idx += stride) {
        int n = idx / KRED, k = idx - n * KRED;
        float v;
        if (k < DD)            v = W_left[n * DD + k];
        else if (k < 2 * DD)   v = W_right[n * DD + (k - DD)];
        else                   v = W_track[n * TRK + (k - 2 * DD)];
        g_Wred[idx] = v;
    }
    for (int idx = tid0; idx < NTRK; idx += stride) g_btrk[idx] = b_ih[idx] + b_hh[idx];
    for (int idx = tid0; idx < BB * TWOD; idx += stride) {
        int b = idx / TWOD, j = idx - b * TWOD;
        float v = buffers[(long)b * TT * TWOD + j];   // buffers[b, 0, j]
        g_stack[((long)b * CAP + 0) * TWOD + j] = v;
        g_stack[((long)b * CAP + 1) * TWOD + j] = v;
    }
    for (int idx = tid0; idx < BB * TRK; idx += stride) { g_th[idx] = 0.f; g_tc[idx] = 0.f; }
    for (int idx = tid0; idx < BB; idx += stride) { g_sptr[idx] = 2; g_blen[idx] = TT; }
    if (tid0 == 0) { g_barCount = 0u; g_barEpoch = 0u; }
}

// ---------------- gather inputs + bias-seed outputs for step 0 --------------
__global__ void k_prep(const float* __restrict__ buffers, const float* __restrict__ b_left) {
    int b = blockIdx.x, tid = threadIdx.x;
    int sptr = g_sptr[b], blen = g_blen[b];
    const float* bt = buffers + ((long)b * TT + (blen - 1)) * TWOD;
    const float* s1 = g_stack + ((long)b * CAP + (sptr - 1)) * TWOD;
    const float* s2 = g_stack + ((long)b * CAP + (sptr - 2)) * TWOD;
    float* xT = g_xT + b * KTRK;
    float* xR = g_xR + b * KXR;
    for (int j = tid; j < DD; j += blockDim.x) {
        xT[j] = bt[j]; xT[DD + j] = s1[j]; xT[2 * DD + j] = s2[j];
        xR[j] = s2[j]; xR[DD + j] = s1[j];
    }
    for (int j = tid; j < TRK; j += blockDim.x) xT[3 * DD + j] = g_th[b * TRK + j];
    for (int j = tid; j < NTRK; j += blockDim.x) g_gates[b * NTRK + j] = g_btrk[j];
    for (int j = tid; j < NRED; j += blockDim.x) g_rin[b * NRED + j] = b_left[j];
}

// ---------------- one GEMM tile: C[128,N-slice] += A-slab * W-slab^T (REDG) -
// 256 threads. BM=128, BN=128, BK=16, microtile 8x8, fma.rn.f32x2, dbl-buffer.
__device__ __noinline__ void gemm_tile(const float* __restrict__ A, int lda,
                                       const float* __restrict__ W, int ldw,
                                       float* __restrict__ C, int N,
                                       int nBase, int kBase, int iters) {
    __shared__ __align__(16) float As[2][16][128];
    __shared__ __align__(16) float Ws[2][16][128];
    int tid = threadIdx.x;
    int tm = (tid & 15) * 8;
    int tn = (tid >> 4) * 8;
    int lrow0 = tid >> 2;
    int lrow1 = lrow0 + 64;
    int lk    = (tid & 3) * 4;

    ull acc[32];
    #pragma unroll
    for (int i = 0; i < 32; i++) acc[i] = 0ull;

    {   // preload slab 0
        float4 a0 = *(const float4*)(A + (long)lrow0 * lda + kBase + lk);
        float4 a1 = *(const float4*)(A + (long)lrow1 * lda + kBase + lk);
        float4 w0 = *(const float4*)(W + (long)(nBase + lrow0) * ldw + kBase + lk);
        float4 w1 = *(const float4*)(W + (long)(nBase + lrow1) * ldw + kBase + lk);
        As[0][lk + 0][lrow0] = a0.x; As[0][lk + 1][lrow0] = a0.y;
        As[0][lk + 2][lrow0] = a0.z; As[0][lk + 3][lrow0] = a0.w;
        As[0][lk + 0][lrow1] = a1.x; As[0][lk + 1][lrow1] = a1.y;
        As[0][lk + 2][lrow1] = a1.z; As[0][lk + 3][lrow1] = a1.w;
        Ws[0][lk + 0][lrow0] = w0.x; Ws[0][lk + 1][lrow0] = w0.y;
        Ws[0][lk + 2][lrow0] = w0.z; Ws[0][lk + 3][lrow0] = w0.w;
        Ws[0][lk + 0][lrow1] = w1.x; Ws[0][lk + 1][lrow1] = w1.y;
        Ws[0][lk + 2][lrow1] = w1.z; Ws[0][lk + 3][lrow1] = w1.w;
    }
    __syncthreads();

    for (int it = 0; it < iters; it++) {
        int buf = it & 1;
        float4 pa0, pa1, pw0, pw1;
        bool more = (it + 1) < iters;
        if (more) {
            int k0 = kBase + (it + 1) * 16;
            pa0 = *(const float4*)(A + (long)lrow0 * lda + k0 + lk);
            pa1 = *(const float4*)(A + (long)lrow1 * lda + k0 + lk);
            pw0 = *(const float4*)(W + (long)(nBase + lrow0) * ldw + k0 + lk);
            pw1 = *(const float4*)(W + (long)(nBase + lrow1) * ldw + k0 + lk);
        }
        #pragma unroll
        for (int kk = 0; kk < 16; kk++) {
            float4 a0 = *(const float4*)&As[buf][kk][tm];
            float4 a1 = *(const float4*)&As[buf][kk][tm + 4];
            ulonglong2 wlo = *(const ulonglong2*)&Ws[buf][kk][tn];
            ulonglong2 whi = *(const ulonglong2*)&Ws[buf][kk][tn + 4];
            float am[8] = {a0.x, a0.y, a0.z, a0.w, a1.x, a1.y, a1.z, a1.w};
            #pragma unroll
            for (int i = 0; i < 8; i++) {
                ull ad = packf2(am[i], am[i]);
                ffma2(acc[i * 4 + 0], ad, wlo.x);
                ffma2(acc[i * 4 + 1], ad, wlo.y);
                ffma2(acc[i * 4 + 2], ad, whi.x);
                ffma2(acc[i * 4 + 3], ad, whi.y);
            }
        }
        if (more) {
            int nb = buf ^ 1;
            As[nb][lk + 0][lrow0] = pa0.x; As[nb][lk + 1][lrow0] = pa0.y;
            As[nb][lk + 2][lrow0] = pa0.z; As[nb][lk + 3][lrow0] = pa0.w;
            As[nb][lk + 0][lrow1] = pa1.x; As[nb][lk + 1][lrow1] = pa1.y;
            As[nb][lk + 2][lrow1] = pa1.z; As[nb][lk + 3][lrow1] = pa1.w;
            Ws[nb][lk + 0][lrow0] = pw0.x; Ws[nb][lk + 1][lrow0] = pw0.y;
            Ws[nb][lk + 2][lrow0] = pw0.z; Ws[nb][lk + 3][lrow0] = pw0.w;
            Ws[nb][lk + 0][lrow1] = pw1.x; Ws[nb][lk + 1][lrow1] = pw1.y;
            Ws[nb][lk + 2][lrow1] = pw1.z; Ws[nb][lk + 3][lrow1] = pw1.w;
            __syncthreads();
        }
    }

    #pragma unroll
    for (int i = 0; i < 8; i++) {
        float2 v0 = unpackf2(acc[i * 4 + 0]);
        float2 v1 = unpackf2(acc[i * 4 + 1]);
        float2 v2 = unpackf2(acc[i * 4 + 2]);
        float2 v3 = unpackf2(acc[i * 4 + 3]);
        float* row = C + (long)(tm + i) * N + nBase + tn;
        redadd(row + 0, v0.x); redadd(row + 1, v0.y);
        redadd(row + 2, v1.x); redadd(row + 3, v1.y);
        redadd(row + 4, v2.x); redadd(row + 5, v2.y);
        redadd(row + 6, v3.x); redadd(row + 7, v3.y);
    }
}

// ---------------- phase-A tile dispatch --------------------------------------
__device__ __forceinline__ void run_tileA(int t, bool more) {
    if (more && t < 160) {                 // reduce-big: 20 n-tiles x 8 splits, 8 slabs
        int nt = t % 20, sp = t / 20;
        gemm_tile(g_xR, KXR, g_Wred, KRED, g_rin, NRED, nt * 128, sp * 8 * 16, 8);
    } else {                               // tracker: 8 n-tiles x 16 splits, 7 slabs
        int tt = more ? (t - 160) : t;
        int nt = tt % 8, sp = tt / 8;
        gemm_tile(g_xT, KTRK, g_Wtrk, KTRK, g_gates, NTRK, nt * 128, sp * 7 * 16, 7);
    }
}

// ---------------- cell: LSTM nonlinearity + logits + argmax ----------------
__device__ void cell_block(int b, const float* __restrict__ W_trans,
                           const float* __restrict__ b_trans,
                           float* __restrict__ out, int step) {
    __shared__ float sp4[4][8];
    int j = threadIdx.x;   // 256 threads, one gate column each
    const float* g = g_gates + b * NTRK;
    float gi = g[j], gf = g[TRK + j], gg = g[2 * TRK + j], go = g[3 * TRK + j];
    float tc = g_tc[b * TRK + j];
    float tcn = sigf(gf) * tc + sigf(gi) * tanhf(gg);
    float thn = sigf(go) * tanhf(tcn);
    g_tc[b * TRK + j] = tcn;
    g_th[b * TRK + j] = thn;

    float p0 = thn * W_trans[0 * TRK + j];
    float p1 = thn * W_trans[1 * TRK + j];
    float p2 = thn * W_trans[2 * TRK + j];
    float p3 = thn * W_trans[3 * TRK + j];
    #pragma unroll
    for (int off = 16; off > 0; off >>= 1) {
        p0 += __shfl_down_sync(0xffffffffu, p0, off);
        p1 += __shfl_down_sync(0xffffffffu, p1, off);
        p2 += __shfl_down_sync(0xffffffffu, p2, off);
        p3 += __shfl_down_sync(0xffffffffu, p3, off);
    }
    if ((j & 31) == 0) {
        int w = j >> 5;
        sp4[0][w] = p0; sp4[1][w] = p1; sp4[2][w] = p2; sp4[3][w] = p3;
    }
    __syncthreads();
    if (j == 0) {
        float l[4];
        #pragma unroll
        for (int t = 0; t < 4; t++) {
            float s = b_trans[t];
            #pragma unroll
            for (int w = 0; w < 8; w++) s += sp4[t][w];
            l[t] = s;
        }
        float* o = out + ((long)step * BB + b) * 4;
        o[0] = l[0]; o[1] = l[1]; o[2] = l[2]; o[3] = l[3];
        int best = 0; float bv = l[0];                     // jnp.argmax: first max
        if (l[1] > bv) { bv = l[1]; best = 1; }
        if (l[2] > bv) { bv = l[2]; best = 2; }
        if (l[3] > bv) { bv = l[3]; best = 3; }
        g_trans[b] = best;
    }
}

// ---------------- epi: TreeLSTM node + stack update + gather + re-seed ------
__device__ void epi_block(int b, const float* __restrict__ buffers,
                          const float* __restrict__ b_left) {
    __shared__ __align__(16) float lin[NRED];
    int tid = threadIdx.x;   // 256 threads
    for (int c4 = tid * 4; c4 < NRED; c4 += 1024)
        *(float4*)&lin[c4] = *(const float4*)&g_rin[b * NRED + c4];
    __syncthreads();

    int sptr = g_sptr[b], blen = g_blen[b];
    int tr = g_trans[b];
    bool do_shift = (tr == 3) && (blen > 2);
    bool do_red   = (tr == 2) && (sptr > 3);
    float* st = g_stack + (long)b * CAP * TWOD;
    const float* bt = buffers + ((long)b * TT + (blen - 1)) * TWOD;

    for (int dd = tid; dd < DD; dd += 256) {
        float a  = lin[dd];
        float i_ = lin[DD + dd];
        float f1 = lin[2 * DD + dd];
        float f2 = lin[3 * DD + dd];
        float o_ = lin[4 * DD + dd];
        float s2c = st[(sptr - 2) * TWOD + DD + dd];
        float s1c = st[(sptr - 1) * TWOD + DD + dd];
        float c = tanhf(a) * sigf(i_) + sigf(f1) * s2c + sigf(f2) * s1c;
        float h = sigf(o_) * tanhf(c);
        if (do_red) {
            st[(sptr - 2) * TWOD + dd]      = h;
            st[(sptr - 2) * TWOD + DD + dd] = c;
        }
        if (do_shift) {
            st[sptr * TWOD + dd]      = bt[dd];
            st[sptr * TWOD + DD + dd] = bt[DD + dd];
        }
    }
    int nsp = sptr + (do_shift ? 1 : 0) - (do_red ? 1 : 0);
    int nbl = blen - (do_shift ? 1 : 0);
    if (tid == 0) { g_sptr[b] = nsp; g_blen[b] = nbl; }
    __syncthreads();

    // gather inputs for next step + re-seed bias accumulators
    const float* nbt = buffers + ((long)b * TT + (nbl - 1)) * TWOD;
    const float* s1 = st + (nsp - 1) * TWOD;
    const float* s2 = st + (nsp - 2) * TWOD;
    float* xT = g_xT + b * KTRK;
    float* xR = g_xR + b * KXR;
    for (int j = tid; j < DD; j += 256) {
        float v1 = s1[j], v2 = s2[j];
        xT[j] = nbt[j]; xT[DD + j] = v1; xT[2 * DD + j] = v2;
        xR[j] = v2;     xR[DD + j] = v1;
    }
    if (tid < TRK) xT[3 * DD + tid] = g_th[b * TRK + tid];
    for (int c4 = tid * 4; c4 < NTRK; c4 += 1024)
        *(float4*)&g_gates[b * NTRK + c4] = *(const float4*)&g_btrk[c4];
    for (int c4 = tid * 4; c4 < NRED; c4 += 1024)
        *(float4*)&g_rin[b * NRED + c4] = *(const float4*)&b_left[c4];
}

// ---------------- persistent main kernel ------------------------------------
__global__ __launch_bounds__(256) void k_main(const float* __restrict__ buffers,
                                              const float* __restrict__ W_trans,
                                              const float* __restrict__ b_trans,
                                              const float* __restrict__ b_left,
                                              float* __restrict__ out, int n_steps) {
    int bx = blockIdx.x;

    for (int s = 0; s < n_steps; s++) {
        bool more = (s + 1 < n_steps);
        // ---- Phase A: both GEMMs, static 2-tile assignment ----
        int nA = more ? NT_A : NT_A_LAST;
        if (bx < nA) run_tileA(bx, more);
        if (bx + NBLK < nA) run_tileA(bx + NBLK, more);
        grid_bar();
        // ---- Phase B: tracker cell (blocks 0..127) ----
        if (bx < BB) cell_block(bx, W_trans, b_trans, out, s);
        if (!more) break;
        grid_bar();
        // ---- Phase C: W_track @ th_new -> g_rin (20 n-tiles x 7 splits) ----
        if (bx < NT_C) {
            int nt = bx % 20, sp = bx / 20;
            int slabS = (sp * 16) / 7, slabE = ((sp + 1) * 16) / 7;
            gemm_tile(g_th, TRK, g_Wred + 2 * DD, KRED, g_rin, NRED,
                      nt * 128, slabS * 16, slabE - slabS);
        }
        grid_bar();
        // ---- Phase D: epi (blocks 0..127) ----
        if (bx < BB) epi_block(bx, buffers, b_left);
        grid_bar();
    }
}

// ---------------------------------------------------------------------------
extern "C" void kernel_launch(void* const* d_in, const int* in_sizes, int n_in,
                              void* d_out, int out_size) {
    const float* buffers = (const float*)d_in[0];
    const float* W_left  = (const float*)d_in[1];
    const float* b_left  = (const float*)d_in[2];
    const float* W_right = (const float*)d_in[3];
    const float* W_track = (const float*)d_in[4];
    const float* W_ih    = (const float*)d_in[5];
    const float* W_hh    = (const float*)d_in[6];
    const float* b_ih    = (const float*)d_in[7];
    const float* b_hh    = (const float*)d_in[8];
    const float* W_trans = (const float*)d_in[9];
    const float* b_trans = (const float*)d_in[10];
    int n_steps = in_sizes[11] / BB;       // transitions: [n_steps, B]
    float* out = (float*)d_out;

    k_init<<<592, 256>>>(buffers, W_ih, W_hh, b_ih, b_hh, W_left, W_right, W_track);
    k_prep<<<BB, 256>>>(buffers, b_left);
    k_main<<<NBLK, 256>>>(buffers, W_trans, b_trans, b_left, out, n_steps);
}

// round 9
// speedup vs baseline: 1.7377x; 1.7377x over previous
#include <cuda_runtime.h>
#include <math.h>

// Problem constants (SPINN1: B=128, T=40, D_HID=512, D_TRK=256)
#define BB   128
#define TT   40
#define DD   512
#define TRK  256
#define CAP  (TT + 2)            // 42
#define TWOD (2 * DD)            // 1024
#define KTRK (3 * DD + TRK)      // 1792  (xT = [buf_h | s1_h | s2_h | th])
#define NTRK (4 * TRK)           // 1024
#define KRED (2 * DD + TRK)      // 1280  (W_red rows: [W_left | W_right | W_track])
#define KXR  (2 * DD)            // 1024  (xR = [s2_h | s1_h])
#define NRED (5 * DD)            // 2560
#define SPLIT_T 7                // tracker split-K: 8n x 7sp tiles, 16 slabs each
#define SPLIT_R 4                // reduce-big split-K: 20n x 4sp tiles, 16 slabs each
#define SPLIT_S 7                // W_track GEMM split-K (2-3 slabs each)
#define SPLIT_RS (SPLIT_R + SPLIT_S)   // 11 unified partial slots for epi
#define NT_TRK (8 * SPLIT_T)     // 56 tracker tiles
#define NT_A   (NT_TRK + 20 * SPLIT_R) // 136 phase-A tiles (one wave)

// ---------------- device state (no runtime allocation allowed) --------------
__device__ __align__(16) float g_stack[BB * CAP * TWOD];
__device__ __align__(16) float g_th[BB * TRK];
__device__ __align__(16) float g_tc[BB * TRK];
__device__ int   g_sptr[BB];
__device__ int   g_blen[BB];
__device__ __align__(16) float g_xT[BB * KTRK];
__device__ __align__(16) float g_xR[BB * KXR];
__device__ __align__(16) float g_partT[SPLIT_T * BB * NTRK];    // 3.7 MB
__device__ __align__(16) float g_partR[SPLIT_RS * BB * NRED];   // 14.4 MB
__device__ int   g_trans[BB];
__device__ __align__(16) float g_Wtrk[NTRK * KTRK];  // [W_ih | W_hh] concat along K
__device__ __align__(16) float g_Wred[NRED * KRED];  // [W_left | W_right | W_track]
__device__ __align__(16) float g_btrk[NTRK];         // b_ih + b_hh

__device__ __forceinline__ float sigf(float x) { return 1.0f / (1.0f + expf(-x)); }

typedef unsigned long long ull;
__device__ __forceinline__ ull packf2(float x, float y) {
    ull v; asm("mov.b64 %0, {%1,%2};" : "=l"(v) : "f"(x), "f"(y)); return v;
}
__device__ __forceinline__ float2 unpackf2(ull v) {
    float2 r; asm("mov.b64 {%0,%1}, %2;" : "=f"(r.x), "=f"(r.y) : "l"(v)); return r;
}
__device__ __forceinline__ void ffma2(ull& d, ull a, ull b) {
    asm("fma.rn.f32x2 %0, %1, %2, %0;" : "+l"(d) : "l"(a), "l"(b));
}

// ---------------- init: concat weights, init stack/state --------------------
__global__ void k_init(const float* __restrict__ buffers,
                       const float* __restrict__ W_ih, const float* __restrict__ W_hh,
                       const float* __restrict__ b_ih, const float* __restrict__ b_hh,
                       const float* __restrict__ W_left, const float* __restrict__ W_right,
                       const float* __restrict__ W_track) {
    int stride = gridDim.x * blockDim.x;
    int tid0 = blockIdx.x * blockDim.x + threadIdx.x;

    for (int idx = tid0; idx < NTRK * KTRK; idx += stride) {
        int n = idx / KTRK, k = idx - n * KTRK;
        g_Wtrk[idx] = (k < 3 * DD) ? W_ih[n * (3 * DD) + k] : W_hh[n * TRK + (k - 3 * DD)];
    }
    for (int idx = tid0; idx < NRED * KRED; idx += stride) {
        int n = idx / KRED, k = idx - n * KRED;
        float v;
        if (k < DD)            v = W_left[n * DD + k];
        else if (k < 2 * DD)   v = W_right[n * DD + (k - DD)];
        else                   v = W_track[n * TRK + (k - 2 * DD)];
        g_Wred[idx] = v;
    }
    for (int idx = tid0; idx < NTRK; idx += stride) g_btrk[idx] = b_ih[idx] + b_hh[idx];
    for (int idx = tid0; idx < BB * TWOD; idx += stride) {
        int b = idx / TWOD, j = idx - b * TWOD;
        float v = buffers[(long)b * TT * TWOD + j];   // buffers[b, 0, j]
        g_stack[((long)b * CAP + 0) * TWOD + j] = v;
        g_stack[((long)b * CAP + 1) * TWOD + j] = v;
    }
    for (int idx = tid0; idx < BB * TRK; idx += stride) { g_th[idx] = 0.f; g_tc[idx] = 0.f; }
    for (int idx = tid0; idx < BB; idx += stride) { g_sptr[idx] = 2; g_blen[idx] = TT; }
}

// ---------------- gather inputs for step 0 ---------------------------------
__global__ void k_prep(const float* __restrict__ buffers) {
    int b = blockIdx.x, tid = threadIdx.x;
    int sptr = g_sptr[b], blen = g_blen[b];
    const float* bt = buffers + ((long)b * TT + (blen - 1)) * TWOD;
    const float* s1 = g_stack + ((long)b * CAP + (sptr - 1)) * TWOD;
    const float* s2 = g_stack + ((long)b * CAP + (sptr - 2)) * TWOD;
    float* xT = g_xT + b * KTRK;
    float* xR = g_xR + b * KXR;
    for (int j = tid; j < DD; j += blockDim.x) {
        xT[j] = bt[j]; xT[DD + j] = s1[j]; xT[2 * DD + j] = s2[j];
        xR[j] = s2[j]; xR[DD + j] = s1[j];
    }
    for (int j = tid; j < TRK; j += blockDim.x) xT[3 * DD + j] = g_th[b * TRK + j];
}

// ---------------- one GEMM tile: Cp[slot][128,N-slice] = A-slab * W-slab^T --
// 256 threads. BM=128, BN=128, BK=16, microtile 8x8, fma.rn.f32x2, dbl-buffer.
__device__ __forceinline__ void gemm_tile(const float* __restrict__ A, int lda,
                                          const float* __restrict__ W, int ldw,
                                          float* __restrict__ Cp, int N,
                                          int nBase, int kBase, int iters) {
    __shared__ __align__(16) float As[2][16][128];
    __shared__ __align__(16) float Ws[2][16][128];
    int tid = threadIdx.x;
    int tm = (tid & 15) * 8;
    int tn = (tid >> 4) * 8;
    int lrow0 = tid >> 2;
    int lrow1 = lrow0 + 64;
    int lk    = (tid & 3) * 4;

    ull acc[32];
    #pragma unroll
    for (int i = 0; i < 32; i++) acc[i] = 0ull;

    {   // preload slab 0
        float4 a0 = *(const float4*)(A + (long)lrow0 * lda + kBase + lk);
        float4 a1 = *(const float4*)(A + (long)lrow1 * lda + kBase + lk);
        float4 w0 = *(const float4*)(W + (long)(nBase + lrow0) * ldw + kBase + lk);
        float4 w1 = *(const float4*)(W + (long)(nBase + lrow1) * ldw + kBase + lk);
        As[0][lk + 0][lrow0] = a0.x; As[0][lk + 1][lrow0] = a0.y;
        As[0][lk + 2][lrow0] = a0.z; As[0][lk + 3][lrow0] = a0.w;
        As[0][lk + 0][lrow1] = a1.x; As[0][lk + 1][lrow1] = a1.y;
        As[0][lk + 2][lrow1] = a1.z; As[0][lk + 3][lrow1] = a1.w;
        Ws[0][lk + 0][lrow0] = w0.x; Ws[0][lk + 1][lrow0] = w0.y;
        Ws[0][lk + 2][lrow0] = w0.z; Ws[0][lk + 3][lrow0] = w0.w;
        Ws[0][lk + 0][lrow1] = w1.x; Ws[0][lk + 1][lrow1] = w1.y;
        Ws[0][lk + 2][lrow1] = w1.z; Ws[0][lk + 3][lrow1] = w1.w;
    }
    __syncthreads();

    for (int it = 0; it < iters; it++) {
        int buf = it & 1;
        float4 pa0, pa1, pw0, pw1;
        bool more = (it + 1) < iters;
        if (more) {
            int k0 = kBase + (it + 1) * 16;
            pa0 = *(const float4*)(A + (long)lrow0 * lda + k0 + lk);
            pa1 = *(const float4*)(A + (long)lrow1 * lda + k0 + lk);
            pw0 = *(const float4*)(W + (long)(nBase + lrow0) * ldw + k0 + lk);
            pw1 = *(const float4*)(W + (long)(nBase + lrow1) * ldw + k0 + lk);
        }
        #pragma unroll
        for (int kk = 0; kk < 16; kk++) {
            float4 a0 = *(const float4*)&As[buf][kk][tm];
            float4 a1 = *(const float4*)&As[buf][kk][tm + 4];
            ulonglong2 wlo = *(const ulonglong2*)&Ws[buf][kk][tn];
            ulonglong2 whi = *(const ulonglong2*)&Ws[buf][kk][tn + 4];
            float am[8] = {a0.x, a0.y, a0.z, a0.w, a1.x, a1.y, a1.z, a1.w};
            #pragma unroll
            for (int i = 0; i < 8; i++) {
                ull ad = packf2(am[i], am[i]);
                ffma2(acc[i * 4 + 0], ad, wlo.x);
                ffma2(acc[i * 4 + 1], ad, wlo.y);
                ffma2(acc[i * 4 + 2], ad, whi.x);
                ffma2(acc[i * 4 + 3], ad, whi.y);
            }
        }
        if (more) {
            int nb = buf ^ 1;
            As[nb][lk + 0][lrow0] = pa0.x; As[nb][lk + 1][lrow0] = pa0.y;
            As[nb][lk + 2][lrow0] = pa0.z; As[nb][lk + 3][lrow0] = pa0.w;
            As[nb][lk + 0][lrow1] = pa1.x; As[nb][lk + 1][lrow1] = pa1.y;
            As[nb][lk + 2][lrow1] = pa1.z; As[nb][lk + 3][lrow1] = pa1.w;
            Ws[nb][lk + 0][lrow0] = pw0.x; Ws[nb][lk + 1][lrow0] = pw0.y;
            Ws[nb][lk + 2][lrow0] = pw0.z; Ws[nb][lk + 3][lrow0] = pw0.w;
            Ws[nb][lk + 0][lrow1] = pw1.x; Ws[nb][lk + 1][lrow1] = pw1.y;
            Ws[nb][lk + 2][lrow1] = pw1.z; Ws[nb][lk + 3][lrow1] = pw1.w;
            __syncthreads();
        }
    }

    #pragma unroll
    for (int i = 0; i < 8; i++) {
        float2 v0 = unpackf2(acc[i * 4 + 0]);
        float2 v1 = unpackf2(acc[i * 4 + 1]);
        float2 v2 = unpackf2(acc[i * 4 + 2]);
        float2 v3 = unpackf2(acc[i * 4 + 3]);
        float* row = Cp + (long)(tm + i) * N + nBase + tn;
        *(float4*)(row)     = make_float4(v0.x, v0.y, v1.x, v1.y);
        *(float4*)(row + 4) = make_float4(v2.x, v2.y, v3.x, v3.y);
    }
}

// ---------------- phase A: both big GEMMs in one wave (136 blocks) ----------
// t < 56: tracker tiles  (8 n-tiles x 7 splits, 16 slabs each, K=1792)
// t >= 56: reduce-big    (20 n-tiles x 4 splits, 16 slabs each, K=1024)
// Launching with grid=56 runs only the tracker part (last step).
__global__ __launch_bounds__(256) void k_gemmA() {
    int t = blockIdx.x;
    if (t < NT_TRK) {
        int nt = t & 7, sp = t / 8;
        gemm_tile(g_xT, KTRK, g_Wtrk, KTRK,
                  g_partT + (size_t)sp * BB * NTRK, NTRK,
                  nt * 128, sp * 16 * 16, 16);
    } else {
        int tt = t - NT_TRK;
        int nt = tt % 20, sp = tt / 20;
        gemm_tile(g_xR, KXR, g_Wred, KRED,
                  g_partR + (size_t)sp * BB * NRED, NRED,
                  nt * 128, sp * 16 * 16, 16);
    }
}

// ---------------- phase C: W_track @ th_new (grid = (20, 7)) ----------------
__global__ __launch_bounds__(256) void k_gemmS() {
    int nt = blockIdx.x, sp = blockIdx.y;
    int slabS = (sp * 16) / SPLIT_S, slabE = ((sp + 1) * 16) / SPLIT_S;
    gemm_tile(g_th, TRK, g_Wred + 2 * DD, KRED,
              g_partR + (size_t)(SPLIT_R + sp) * BB * NRED, NRED,
              nt * 128, slabS * 16, slabE - slabS);
}

// ---------------- tracker LSTM cell + logits + argmax (512 threads) --------
__global__ __launch_bounds__(512) void k_cell(const float* __restrict__ W_trans,
                                              const float* __restrict__ b_trans,
                                              float* __restrict__ out, int step) {
    int b = blockIdx.x, tid = threadIdx.x;   // 512 threads
    __shared__ __align__(16) float part[2][NTRK];
    __shared__ float sp4[4][8];
    {   // slot-split partial sum: half threads take slots 0-3(+bias), half 4-6
        int g = (tid & 255) * 4;
        int h = tid >> 8;
        float4 s;
        if (h == 0) {
            s = *(const float4*)&g_btrk[g];
            #pragma unroll
            for (int sp = 0; sp < 4; sp++) {
                float4 v = *(const float4*)&g_partT[((size_t)sp * BB + b) * NTRK + g];
                s.x += v.x; s.y += v.y; s.z += v.z; s.w += v.w;
            }
        } else {
            s = make_float4(0.f, 0.f, 0.f, 0.f);
            #pragma unroll
            for (int sp = 4; sp < SPLIT_T; sp++) {
                float4 v = *(const float4*)&g_partT[((size_t)sp * BB + b) * NTRK + g];
                s.x += v.x; s.y += v.y; s.z += v.z; s.w += v.w;
            }
        }
        *(float4*)&part[h][g] = s;
    }
    __syncthreads();

    if (tid < 256) {
        int j = tid;
        float gi = part[0][j] + part[1][j];
        float gf = part[0][TRK + j] + part[1][TRK + j];
        float gg = part[0][2 * TRK + j] + part[1][2 * TRK + j];
        float go = part[0][3 * TRK + j] + part[1][3 * TRK + j];
        float tc = g_tc[b * TRK + j];
        float tcn = sigf(gf) * tc + sigf(gi) * tanhf(gg);
        float thn = sigf(go) * tanhf(tcn);
        g_tc[b * TRK + j] = tcn;
        g_th[b * TRK + j] = thn;

        float p0 = thn * W_trans[0 * TRK + j];
        float p1 = thn * W_trans[1 * TRK + j];
        float p2 = thn * W_trans[2 * TRK + j];
        float p3 = thn * W_trans[3 * TRK + j];
        #pragma unroll
        for (int off = 16; off > 0; off >>= 1) {
            p0 += __shfl_down_sync(0xffffffffu, p0, off);
            p1 += __shfl_down_sync(0xffffffffu, p1, off);
            p2 += __shfl_down_sync(0xffffffffu, p2, off);
            p3 += __shfl_down_sync(0xffffffffu, p3, off);
        }
        if ((j & 31) == 0) {
            int w = j >> 5;
            sp4[0][w] = p0; sp4[1][w] = p1; sp4[2][w] = p2; sp4[3][w] = p3;
        }
    }
    __syncthreads();
    if (tid == 0) {
        float l[4];
        #pragma unroll
        for (int t = 0; t < 4; t++) {
            float s = b_trans[t];
            #pragma unroll
            for (int w = 0; w < 8; w++) s += sp4[t][w];
            l[t] = s;
        }
        float* o = out + ((long)step * BB + b) * 4;
        o[0] = l[0]; o[1] = l[1]; o[2] = l[2]; o[3] = l[3];
        int best = 0; float bv = l[0];                     // jnp.argmax: first max
        if (l[1] > bv) { bv = l[1]; best = 1; }
        if (l[2] > bv) { bv = l[2]; best = 2; }
        if (l[3] > bv) { bv = l[3]; best = 3; }
        g_trans[b] = best;
    }
}

// ---------------- TreeLSTM epilogue + stack update + gather for next -------
// 640 threads: float4 sums of 11 unified partial slots, then node + gather.
__global__ __launch_bounds__(640) void k_epi(const float* __restrict__ buffers,
                                             const float* __restrict__ b_left) {
    __shared__ __align__(16) float lin[NRED];
    int b = blockIdx.x, tid = threadIdx.x;   // 640 threads
    {
        int c4 = tid * 4;                    // covers all 2560 columns
        float4 s = *(const float4*)&b_left[c4];
        #pragma unroll
        for (int sp = 0; sp < SPLIT_RS; sp++) {
            float4 v = *(const float4*)&g_partR[((size_t)sp * BB + b) * NRED + c4];
            s.x += v.x; s.y += v.y; s.z += v.z; s.w += v.w;
        }
        *(float4*)&lin[c4] = s;
    }
    __syncthreads();

    int sptr = g_sptr[b], blen = g_blen[b];
    int tr = g_trans[b];
    bool do_shift = (tr == 3) && (blen > 2);
    bool do_red   = (tr == 2) && (sptr > 3);
    float* st = g_stack + (long)b * CAP * TWOD;
    const float* bt = buffers + ((long)b * TT + (blen - 1)) * TWOD;

    if (tid < DD) {
        int dd = tid;
        float a  = lin[dd];
        float i_ = lin[DD + dd];
        float f1 = lin[2 * DD + dd];
        float f2 = lin[3 * DD + dd];
        float o_ = lin[4 * DD + dd];
        float s2c = st[(sptr - 2) * TWOD + DD + dd];
        float s1c = st[(sptr - 1) * TWOD + DD + dd];
        float c = tanhf(a) * sigf(i_) + sigf(f1) * s2c + sigf(f2) * s1c;
        float h = sigf(o_) * tanhf(c);
        if (do_red) {
            st[(sptr - 2) * TWOD + dd]      = h;
            st[(sptr - 2) * TWOD + DD + dd] = c;
        }
        if (do_shift) {
            st[sptr * TWOD + dd]      = bt[dd];
            st[sptr * TWOD + DD + dd] = bt[DD + dd];
        }
    }
    int nsp = sptr + (do_shift ? 1 : 0) - (do_red ? 1 : 0);
    int nbl = blen - (do_shift ? 1 : 0);
    if (tid == 0) { g_sptr[b] = nsp; g_blen[b] = nbl; }
    __syncthreads();

    // gather inputs for next step
    const float* nbt = buffers + ((long)b * TT + (nbl - 1)) * TWOD;
    const float* s1 = st + (nsp - 1) * TWOD;
    const float* s2 = st + (nsp - 2) * TWOD;
    float* xT = g_xT + b * KTRK;
    float* xR = g_xR + b * KXR;
    if (tid < DD) {
        int j = tid;
        float v1 = s1[j], v2 = s2[j];
        xT[j] = nbt[j]; xT[DD + j] = v1; xT[2 * DD + j] = v2;
        xR[j] = v2;     xR[DD + j] = v1;
    } else {
        // threads 512..639 copy BOTH halves of th (j and j+128) -> full TRK=256
        int j = tid - DD;
        xT[3 * DD + j]       = g_th[b * TRK + j];
        xT[3 * DD + j + 128] = g_th[b * TRK + j + 128];
    }
}

// ---------------------------------------------------------------------------
extern "C" void kernel_launch(void* const* d_in, const int* in_sizes, int n_in,
                              void* d_out, int out_size) {
    const float* buffers = (const float*)d_in[0];
    const float* W_left  = (const float*)d_in[1];
    const float* b_left  = (const float*)d_in[2];
    const float* W_right = (const float*)d_in[3];
    const float* W_track = (const float*)d_in[4];
    const float* W_ih    = (const float*)d_in[5];
    const float* W_hh    = (const float*)d_in[6];
    const float* b_ih    = (const float*)d_in[7];
    const float* b_hh    = (const float*)d_in[8];
    const float* W_trans = (const float*)d_in[9];
    const float* b_trans = (const float*)d_in[10];
    int n_steps = in_sizes[11] / BB;       // transitions: [n_steps, B]
    float* out = (float*)d_out;

    k_init<<<592, 256>>>(buffers, W_ih, W_hh, b_ih, b_hh, W_left, W_right, W_track);
    k_prep<<<BB, 256>>>(buffers);

    for (int s = 0; s < n_steps; s++) {
        bool more = (s + 1 < n_steps);
        // phase A: tracker + reduce-big GEMMs in one 136-block wave
        k_gemmA<<<more ? NT_A : NT_TRK, 256>>>();
        k_cell<<<BB, 512>>>(W_trans, b_trans, out, s);
        if (more) {
            k_gemmS<<<dim3(20, SPLIT_S), 256>>>();
            k_epi<<<BB, 640>>>(buffers, b_left);
        }
    }
}